// round 11
// baseline (speedup 1.0000x reference)
#include <cuda_runtime.h>
#include <cuda_bf16.h>
#include <cstdint>

#define Cc 128
#define Gg 2000

// ---------------- scratch (device globals; no allocation) ----------------
__device__ float d_ce_g[Cc * 64];
__device__ float d_A_g[Cc * 256];
__device__ float d_B_g[Gg * 256];
__device__ float d_p_g[Gg * 256];
__device__ float d_q_g[Gg * 256];
__device__ float d_cg_g[Gg];
__device__ float d_x3_g[Gg * Cc];
__device__ __nv_bfloat16 d_Wt16[256 * 256];          // W2a^T bf16 [n][k]
__device__ __nv_bfloat16 d_x16[(size_t)Gg * 128 * 256]; // cached x bf16 [g][c][k]

__device__ __forceinline__ float eluf(float x) {
    return x > 0.f ? x : (__expf(x) - 1.f);
}
// branchless exact elu: max(x,0) + e^{min(x,0)} - 1
__device__ __forceinline__ float melu(float x) {
    return fmaxf(x, 0.f) + __expf(fminf(x, 0.f)) - 1.f;
}

__device__ __forceinline__ void mma_bf16(float* acc, const unsigned* a, const unsigned* b) {
    asm volatile(
        "mma.sync.aligned.m16n8k16.row.col.f32.bf16.bf16.f32 "
        "{%0,%1,%2,%3}, {%4,%5,%6,%7}, {%8,%9}, {%0,%1,%2,%3};"
        : "+f"(acc[0]), "+f"(acc[1]), "+f"(acc[2]), "+f"(acc[3])
        : "r"(a[0]), "r"(a[1]), "r"(a[2]), "r"(a[3]), "r"(b[0]), "r"(b[1]));
}
__device__ __forceinline__ void ldsm4(unsigned& r0, unsigned& r1, unsigned& r2, unsigned& r3,
                                      uint32_t addr) {
    asm volatile("ldmatrix.sync.aligned.m8n8.x4.shared.b16 {%0,%1,%2,%3}, [%4];"
                 : "=r"(r0), "=r"(r1), "=r"(r2), "=r"(r3) : "r"(addr));
}
__device__ __forceinline__ uint32_t smem_u32(const void* p) {
    uint32_t a;
    asm("{ .reg .u64 t; cvta.to.shared.u64 t, %1; cvt.u32.u64 %0, t; }" : "=r"(a) : "l"(p));
    return a;
}
__device__ __forceinline__ void cpasync16(uint32_t dst, const void* src) {
    asm volatile("cp.async.ca.shared.global [%0], [%1], 16;" :: "r"(dst), "l"(src));
}
__device__ __forceinline__ void cp_commit() { asm volatile("cp.async.commit_group;"); }
template <int N> __device__ __forceinline__ void cp_wait() {
    asm volatile("cp.async.wait_group %0;" :: "n"(N));
}

// ---------------- k_ce ----------------
__global__ __launch_bounds__(1024) void k_ce(
    const float* __restrict__ ctrl, const float* __restrict__ ce_w1,
    const float* __restrict__ ce_b1, const float* __restrict__ ce_w2,
    const float* __restrict__ ce_b2)
{
    int c = blockIdx.x, tid = threadIdx.x;
    __shared__ float row[Gg];
    __shared__ float part[4][256];
    __shared__ float h1[256];
    for (int i = tid; i < Gg; i += 1024) row[i] = ctrl[c * Gg + i];
    __syncthreads();
    int sl = tid >> 8, t = tid & 255;
    float acc = 0.f;
    for (int k = sl * 500; k < sl * 500 + 500; k++)
        acc += row[k] * ce_w1[k * 256 + t];
    part[sl][t] = acc;
    __syncthreads();
    if (tid < 256) {
        float v = part[0][tid] + part[1][tid] + part[2][tid] + part[3][tid] + ce_b1[tid];
        h1[tid] = eluf(v);
    }
    __syncthreads();
    if (tid < 256) {
        int s2 = tid >> 6, e = tid & 63;
        float a2 = 0.f;
        for (int h = s2 * 64; h < s2 * 64 + 64; h++)
            a2 += h1[h] * ce_w2[h * 64 + e];
        part[s2][e] = a2;
    }
    __syncthreads();
    if (tid < 64)
        d_ce_g[c * 64 + tid] = part[0][tid] + part[1][tid] + part[2][tid] + part[3][tid] + ce_b2[tid];
}

// ---- k_AT: blocks [0,128) = k_A; blocks [128,192) = W2a transpose->bf16 ----
__global__ __launch_bounds__(256) void k_AT(const float* __restrict__ g_w1,
                                            const float* __restrict__ g_w2)
{
    __shared__ float shb[32][33];   // used by both branches (k_A uses row 0 area)
    if (blockIdx.x < 128) {
        int c = blockIdx.x, tid = threadIdx.x;
        float* ces = &shb[0][0];
        if (tid < 64) ces[tid] = d_ce_g[c * 64 + tid];
        __syncthreads();
        float a = 0.f;
#pragma unroll 8
        for (int e = 0; e < 64; e++)
            a += ces[e] * g_w1[(1 + e) * 256 + tid];
        d_A_g[c * 256 + tid] = a;
    } else {
        int bid = blockIdx.x - 128;
        int bx = bid & 7, by = bid >> 3;
        int tx = threadIdx.x & 31, ty = threadIdx.x >> 5;
        int k0 = bx * 32, n0 = by * 32;
#pragma unroll
        for (int p = 0; p < 4; p++)
            shb[ty + 8 * p][tx] = g_w2[(k0 + ty + 8 * p) * 256 + n0 + tx];
        __syncthreads();
#pragma unroll
        for (int p = 0; p < 4; p++)
            d_Wt16[(n0 + ty + 8 * p) * 256 + k0 + tx] = __float2bfloat16(shb[tx][ty + 8 * p]);
    }
}

// ---------------- k_B ----------------
__global__ void k_B(const int* __restrict__ gidx, const float* __restrict__ shift_vec,
                    const float* __restrict__ gene_table, const float* __restrict__ g_w1,
                    const float* __restrict__ g_b1)
{
    int g = blockIdx.x, tid = threadIdx.x;
    __shared__ float ges[64];
    __shared__ float shs;
    int gs = gidx[g];
    if (tid < 64) ges[tid] = gene_table[gs * 64 + tid];
    if (tid == 0) shs = shift_vec[gs];
    __syncthreads();
    float a = g_b1[tid] + 128.0f * g_w1[130 * 256 + tid] + shs * g_w1[129 * 256 + tid];
#pragma unroll 8
    for (int e = 0; e < 64; e++)
        a += ges[e] * g_w1[(65 + e) * 256 + tid];
    d_B_g[g * 256 + tid] = a;
}

// ---- k_px: compute x once; cache bf16 to gmem; p[g,h] = mean_c x ----
__global__ __launch_bounds__(256) void k_px(
    const float* __restrict__ ctrl, const int* __restrict__ gidx,
    const float* __restrict__ g_w1)
{
    int g = blockIdx.x, tid = threadIdx.x;
    int hp = tid & 127, cr = tid >> 7;    // h-pair (2hp,2hp+1); c parity
    __shared__ float cs[128];
    __shared__ float part[2][256];
    int gs = gidx[g];
    if (tid < 128) cs[tid] = ctrl[tid * Gg + gs];
    __syncthreads();
    float2 rv = *(const float2*)(g_w1 + 2 * hp);
    float2 Bv = *(const float2*)(d_B_g + g * 256 + 2 * hp);
    float s0 = 0.f, s1 = 0.f;
    unsigned* xout = (unsigned*)d_x16 + (size_t)g * 16384 + hp;
#pragma unroll 4
    for (int c = cr; c < 128; c += 2) {
        float2 av = *(const float2*)(d_A_g + c * 256 + 2 * hp);
        float cv = cs[c];
        float v0 = melu(fmaf(cv, rv.x, av.x + Bv.x));
        float v1 = melu(fmaf(cv, rv.y, av.y + Bv.y));
        s0 += v0; s1 += v1;
        unsigned pr;
        asm("cvt.rn.bf16x2.f32 %0, %1, %2;" : "=r"(pr) : "f"(v1), "f"(v0));
        xout[c * 128] = pr;
    }
    part[cr][2 * hp]     = s0;
    part[cr][2 * hp + 1] = s1;
    __syncthreads();
    d_p_g[g * 256 + tid] = (part[0][tid] + part[1][tid]) * (1.f / 128.f);
}

// ---- k_q: q = p@W2b + b2 ; p2 = p@W2a + q ; cg = sum w3b*elu(p2) + b3 ----
__global__ __launch_bounds__(256) void k_q(
    const float* __restrict__ g_w2, const float* __restrict__ g_b2,
    const float* __restrict__ g_w3, const float* __restrict__ g_b3)
{
    __shared__ float ps[8][256];
    __shared__ float red[8][256];
    int g0 = blockIdx.x * 8, tid = threadIdx.x;
    for (int i = 0; i < 8; i++) ps[i][tid] = d_p_g[(g0 + i) * 256 + tid];
    __syncthreads();
    float qa[8], pa[8];
#pragma unroll
    for (int i = 0; i < 8; i++) { qa[i] = 0.f; pa[i] = 0.f; }
    for (int k = 0; k < 256; k++) {
        float wa = g_w2[k * 256 + tid];
        float wb = g_w2[(256 + k) * 256 + tid];
#pragma unroll
        for (int i = 0; i < 8; i++) {
            float pv = ps[i][k];
            qa[i] = fmaf(pv, wb, qa[i]);
            pa[i] = fmaf(pv, wa, pa[i]);
        }
    }
    float b2v = g_b2[tid];
    float w3bv = g_w3[256 + tid];
#pragma unroll
    for (int i = 0; i < 8; i++) {
        float q = qa[i] + b2v;
        d_q_g[(g0 + i) * 256 + tid] = q;
        float p2 = pa[i] + q;
        red[i][tid] = w3bv * eluf(p2);
    }
    __syncthreads();
    for (int off = 128; off > 0; off >>= 1) {
        if (tid < off)
#pragma unroll
            for (int i = 0; i < 8; i++) red[i][tid] += red[i][tid + off];
        __syncthreads();
    }
    if (tid < 8) d_cg_g[g0 + tid] = red[tid][0] + g_b3[0];
}

// ======= k3: per-(gene, M-half) bf16 GEMM, pure cp.async + ldsm + mma =====
// W ring 3 x [256 n][20w]; X ring 3 x [64 c][20w].
#define WBASE   0
#define WBUFW   5120
#define XBASE   15360
#define XBUFW   1280
#define SM_QS   19200
#define SM_W3A  19456
#define SM_RR   19712
#define K3_WORDS 19968   // 79872 bytes -> 2 blocks/SM

__global__ __launch_bounds__(256, 2) void k3(const float* __restrict__ g_w3)
{
    extern __shared__ float sm[];
    uint32_t sbase = smem_u32(sm);

    int bi = blockIdx.x;
    int g = bi >> 1, mh = bi & 1;
    int tid = threadIdx.x;
    int lane = tid & 31, w = tid >> 5;
    int lg = lane >> 2, lt = lane & 3;
    int wr = w >> 2, wc = w & 3;          // 2 x 4 warps; warp tile 32r x 64c
    int m8 = lane >> 3, r8 = lane & 7;

    sm[SM_QS + tid]  = d_q_g[g * 256 + tid];
    sm[SM_W3A + tid] = g_w3[tid];

    auto CPW = [&](int kc, int buf) {
        for (int i = tid; i < 1024; i += 256) {
            int row = i >> 2, seg = i & 3;
            cpasync16(sbase + (WBASE + buf * WBUFW + row * 20 + seg * 4) * 4,
                      d_Wt16 + row * 256 + kc * 32 + seg * 8);
        }
    };
    auto CPX = [&](int kc, int buf) {
        int row = tid >> 2, seg = tid & 3;   // 256 threads: rows 0..63, segs 0..3
        cpasync16(sbase + (XBASE + buf * XBUFW + row * 20 + seg * 4) * 4,
                  d_x16 + ((size_t)g * 128 + mh * 64 + row) * 256 + kc * 32 + seg * 8);
    };

    CPW(0, 0); CPX(0, 0); cp_commit();
    CPW(1, 1); CPX(1, 1); cp_commit();
    cp_wait<1>();
    __syncthreads();

    float acc[2][8][4];
#pragma unroll
    for (int i = 0; i < 2; i++)
#pragma unroll
        for (int j = 0; j < 8; j++)
#pragma unroll
            for (int k = 0; k < 4; k++) acc[i][j][k] = 0.f;

#pragma unroll
    for (int kc = 0; kc < 8; kc++) {
        uint32_t xbb = sbase + (XBASE + (kc % 3) * XBUFW) * 4;
        uint32_t wbb = sbase + (WBASE + (kc % 3) * WBUFW) * 4;
#pragma unroll
        for (int ks = 0; ks < 2; ks++) {
            int k0b = ks * 32;
            unsigned a[2][4], b[8][2];
#pragma unroll
            for (int ra = 0; ra < 2; ra++) {
                uint32_t addr = xbb + (wr * 32 + ra * 16 + (m8 & 1) * 8 + r8) * 80
                              + k0b + (m8 >> 1) * 16;
                ldsm4(a[ra][0], a[ra][1], a[ra][2], a[ra][3], addr);
            }
#pragma unroll
            for (int cbp = 0; cbp < 4; cbp++) {
                uint32_t addr = wbb + (wc * 64 + (2 * cbp + (m8 >> 1)) * 8 + r8) * 80
                              + k0b + (m8 & 1) * 16;
                ldsm4(b[2 * cbp][0], b[2 * cbp][1], b[2 * cbp + 1][0], b[2 * cbp + 1][1], addr);
            }
#pragma unroll
            for (int ra = 0; ra < 2; ra++)
#pragma unroll
                for (int cb = 0; cb < 8; cb++)
                    mma_bf16(acc[ra][cb], a[ra], b[cb]);
        }
        if (kc < 6) {
            CPW(kc + 2, (kc + 2) % 3); CPX(kc + 2, (kc + 2) % 3); cp_commit();
            cp_wait<1>();
        } else if (kc == 6) {
            cp_wait<0>();
        }
        __syncthreads();
    }

    // -------- epilogue: row sums of w3a * elu(x2 + q) --------
    float rsum[2][2];
    rsum[0][0] = rsum[0][1] = rsum[1][0] = rsum[1][1] = 0.f;
#pragma unroll
    for (int ra = 0; ra < 2; ra++) {
#pragma unroll
        for (int cb = 0; cb < 8; cb++) {
#pragma unroll
            for (int jj = 0; jj < 4; jj++) {
                int col = wc * 64 + cb * 8 + 2 * lt + (jj & 1);
                float v = acc[ra][cb][jj] + sm[SM_QS + col];
                rsum[ra][jj >> 1] += sm[SM_W3A + col] * melu(v);
            }
        }
    }
#pragma unroll
    for (int m = 1; m <= 2; m <<= 1)
#pragma unroll
        for (int ra = 0; ra < 2; ra++) {
            rsum[ra][0] += __shfl_xor_sync(0xffffffffu, rsum[ra][0], m);
            rsum[ra][1] += __shfl_xor_sync(0xffffffffu, rsum[ra][1], m);
        }
    if (lt == 0) {
#pragma unroll
        for (int ra = 0; ra < 2; ra++) {
            sm[SM_RR + wc * 64 + wr * 32 + ra * 16 + lg]     = rsum[ra][0];
            sm[SM_RR + wc * 64 + wr * 32 + ra * 16 + 8 + lg] = rsum[ra][1];
        }
    }
    __syncthreads();
    if (tid < 64)
        d_x3_g[g * 128 + mh * 64 + tid] =
            sm[SM_RR + tid] + sm[SM_RR + 64 + tid] +
            sm[SM_RR + 128 + tid] + sm[SM_RR + 192 + tid];
}

// ---- k4: + cgene, softmax over cells ----
__global__ __launch_bounds__(128) void k4(float* __restrict__ out)
{
    int g = blockIdx.x, tid = threadIdx.x;
    __shared__ float buf[128];
    float v = d_x3_g[g * 128 + tid] + d_cg_g[g];
    buf[tid] = v;
    __syncthreads();
    for (int off = 64; off > 0; off >>= 1) {
        if (tid < off) buf[tid] = fmaxf(buf[tid], buf[tid + off]);
        __syncthreads();
    }
    float m = buf[0];
    __syncthreads();
    float e = __expf(v - m);
    buf[tid] = e;
    __syncthreads();
    for (int off = 64; off > 0; off >>= 1) {
        if (tid < off) buf[tid] += buf[tid + off];
        __syncthreads();
    }
    out[tid * Gg + g] = e / buf[0];
}

// -------------------------------------------------------------------------
extern "C" void kernel_launch(void* const* d_in, const int* in_sizes, int n_in,
                              void* d_out, int out_size)
{
    const float* ctrl       = (const float*)d_in[0];
    const float* shift_vec  = (const float*)d_in[1];
    const int*   gidx       = (const int*)d_in[2];
    const float* ce_w1      = (const float*)d_in[3];
    const float* ce_b1      = (const float*)d_in[4];
    const float* ce_w2      = (const float*)d_in[5];
    const float* ce_b2      = (const float*)d_in[6];
    const float* gene_table = (const float*)d_in[7];
    const float* g_w1       = (const float*)d_in[8];
    const float* g_b1       = (const float*)d_in[9];
    const float* g_w2       = (const float*)d_in[10];
    const float* g_b2       = (const float*)d_in[11];
    const float* g_w3       = (const float*)d_in[12];
    const float* g_b3       = (const float*)d_in[13];
    float* out = (float*)d_out;

    cudaFuncSetAttribute(k3, cudaFuncAttributeMaxDynamicSharedMemorySize,
                         K3_WORDS * (int)sizeof(float));

    k_ce<<<Cc, 1024>>>(ctrl, ce_w1, ce_b1, ce_w2, ce_b2);
    k_AT<<<192, 256>>>(g_w1, g_w2);
    k_B<<<Gg, 256>>>(gidx, shift_vec, gene_table, g_w1, g_b1);
    k_px<<<Gg, 256>>>(ctrl, gidx, g_w1);
    k_q<<<Gg / 8, 256>>>(g_w2, g_b2, g_w3, g_b3);
    k3<<<2 * Gg, 256, K3_WORDS * sizeof(float)>>>(g_w3);
    k4<<<Gg, 128>>>(out);
}